// round 5
// baseline (speedup 1.0000x reference)
#include <cuda_runtime.h>
#include <cuda_bf16.h>
#include <cstdint>

#define N_NODES 50000
#define N_EDGES 800000
#define DIN 128
#define DH  256
#define DOUT 64
#define NB_SCAN 49   // ceil(50000/1024)

// ---------------- scratch ------------------------------------------------------
__device__ __align__(16) float g_agg1[N_NODES * DIN];
__device__ __align__(16) float g_inv [N_NODES];
__device__ __align__(16) float g_h   [N_NODES * DH];
__device__ __align__(16) float g_P   [N_NODES * 2*DOUT];
__device__ int g_rowptr[N_NODES + 1];
__device__ int g_cnt   [N_NODES];
__device__ int g_col   [N_EDGES];
__device__ int g_bsum  [64];
__device__ int g_boff  [64];
__device__ int g_is64;

// ---------------- zero counts + edge dtype detect (fused) ----------------------
__global__ void zero_cnt_detect_kernel(const unsigned int* __restrict__ ei_words) {
    int i = blockIdx.x * blockDim.x + threadIdx.x;
    if (i < N_NODES) g_cnt[i] = 0;
    if (i == 0) {
        int is64 = 1;
        for (int k = 0; k < 128; ++k)
            if (ei_words[2 * k + 1] != 0u) { is64 = 0; break; }
        g_is64 = is64;
    }
}
__device__ __forceinline__ long long edge_val(const void* ei, long long idx) {
    if (g_is64) return ((const long long*)ei)[idx];
    return (long long)((const int*)ei)[idx];
}

__global__ void count_kernel(const void* __restrict__ ei) {
    int e = blockIdx.x * blockDim.x + threadIdx.x;
    if (e >= N_EDGES) return;
    long long d = edge_val(ei, N_EDGES + e);
    if ((unsigned long long)d < N_NODES) atomicAdd(&g_cnt[(int)d], 1);
}

// pass 1: per-block sums (1024 elems / block)
__global__ void blocksum_kernel() {
    int b = blockIdx.x, t = threadIdx.x;
    int i0 = b * 1024 + t * 4;
    int s = 0;
#pragma unroll
    for (int k = 0; k < 4; ++k) { int i = i0 + k; if (i < N_NODES) s += g_cnt[i]; }
    for (int off = 16; off > 0; off >>= 1) s += __shfl_down_sync(0xffffffffu, s, off);
    __shared__ int ws[8];
    int lane = t & 31, w = t >> 5;
    if (lane == 0) ws[w] = s;
    __syncthreads();
    if (t == 0) { int tot = 0; for (int k = 0; k < 8; ++k) tot += ws[k]; g_bsum[b] = tot; }
}
// pass 2: exclusive scan of 49 block sums
__global__ void bscan_kernel() {
    __shared__ int sv[64];
    int t = threadIdx.x;
    int v = (t < NB_SCAN) ? g_bsum[t] : 0;
    sv[t] = v;
    __syncthreads();
    for (int off = 1; off < 64; off <<= 1) {
        int u = (t >= off) ? sv[t - off] : 0;
        __syncthreads();
        sv[t] += u;
        __syncthreads();
    }
    g_boff[t] = sv[t] - v;
}
// pass 3: per-block scan + rowptr + cursor + inv-degree (fused)
__global__ void rowptr_kernel() {
    __shared__ int warp_tot[8];
    __shared__ int warp_off[8];
    int b = blockIdx.x, t = threadIdx.x;
    int lane = t & 31, w = t >> 5;
    int i0 = b * 1024 + t * 4;
    int c[4];
#pragma unroll
    for (int k = 0; k < 4; ++k) { int i = i0 + k; c[k] = (i < N_NODES) ? g_cnt[i] : 0; }
    int s = c[0] + c[1] + c[2] + c[3];
    int pre = s;
    for (int off = 1; off < 32; off <<= 1) {
        int n = __shfl_up_sync(0xffffffffu, pre, off);
        if (lane >= off) pre += n;
    }
    if (lane == 31) warp_tot[w] = pre;
    __syncthreads();
    if (w == 0) {
        int v = (lane < 8) ? warp_tot[lane] : 0;
        int orig = v;
        for (int off = 1; off < 8; off <<= 1) {
            int n = __shfl_up_sync(0xffffffffu, v, off);
            if (lane >= off) v += n;
        }
        if (lane < 8) warp_off[lane] = v - orig;
    }
    __syncthreads();
    int r = g_boff[b] + warp_off[w] + (pre - s);
#pragma unroll
    for (int k = 0; k < 4; ++k) {
        int i = i0 + k;
        if (i < N_NODES) {
            g_rowptr[i] = r;
            g_cnt[i]    = r;  // fill cursor
            g_inv[i]    = 1.0f / (float)(c[k] > 0 ? c[k] : 1);
            r += c[k];
            if (i == N_NODES - 1) g_rowptr[N_NODES] = r;
        }
    }
}
__global__ void fill_kernel(const void* __restrict__ ei) {
    int e = blockIdx.x * blockDim.x + threadIdx.x;
    if (e >= N_EDGES) return;
    long long s = edge_val(ei, e);
    long long d = edge_val(ei, N_EDGES + e);
    if ((unsigned long long)s >= N_NODES || (unsigned long long)d >= N_NODES) return;
    int pos = atomicAdd(&g_cnt[(int)d], 1);
    g_col[pos] = (int)s;
}

// ---------------- layer-1 aggregation (gather, warp per node) ------------------
__global__ void __launch_bounds__(256)
agg1_kernel(const float* __restrict__ x) {
    int w    = (blockIdx.x * blockDim.x + threadIdx.x) >> 5;
    int lane = threadIdx.x & 31;
    if (w >= N_NODES) return;
    int start = g_rowptr[w], end = g_rowptr[w + 1];
    const float4* xv = (const float4*)x;
    float4 acc = make_float4(0.f, 0.f, 0.f, 0.f);
    int p = start;
    for (; p + 4 <= end; p += 4) {
        int s0 = g_col[p], s1 = g_col[p + 1], s2 = g_col[p + 2], s3 = g_col[p + 3];
        float4 v0 = xv[(long long)s0 * 32 + lane];
        float4 v1 = xv[(long long)s1 * 32 + lane];
        float4 v2 = xv[(long long)s2 * 32 + lane];
        float4 v3 = xv[(long long)s3 * 32 + lane];
        acc.x += v0.x + v1.x + v2.x + v3.x;
        acc.y += v0.y + v1.y + v2.y + v3.y;
        acc.z += v0.z + v1.z + v2.z + v3.z;
        acc.w += v0.w + v1.w + v2.w + v3.w;
    }
    for (; p < end; ++p) {
        float4 v = xv[(long long)g_col[p] * 32 + lane];
        acc.x += v.x; acc.y += v.y; acc.z += v.z; acc.w += v.w;
    }
    float inv = g_inv[w];
    acc.x *= inv; acc.y *= inv; acc.z *= inv; acc.w *= inv;
    ((float4*)g_agg1)[(long long)w * 32 + lane] = acc;
}

// ================= bf16x3 tensor-core GEMM (double-buffered) ====================
// block tile 128x128, 8 warps, warp tile 32x64, K-chunk 32 fp32 (2 k16 steps)
#define SM_LD 40            // bf16 row stride (32 + 8 pad)
#define TILE_HALF (128 * SM_LD)          // one hi or lo tile, in bf16 elems
#define BUF_ELEMS (4 * TILE_HALF)        // Ahi,Alo,Bhi,Blo
// dynamic smem: 2 * BUF_ELEMS * 2 bytes = 81920 B

__device__ __forceinline__ uint32_t pack_bf16x2(__nv_bfloat16 a, __nv_bfloat16 b) {
    return (uint32_t)__bfloat16_as_ushort(a) | ((uint32_t)__bfloat16_as_ushort(b) << 16);
}
__device__ __forceinline__ void split2(float v, __nv_bfloat16& h, __nv_bfloat16& l) {
    h = __float2bfloat16(v);
    l = __float2bfloat16(v - __bfloat162float(h));
}
__device__ __forceinline__ void lds_x4(uint32_t addr, uint32_t& r0, uint32_t& r1,
                                       uint32_t& r2, uint32_t& r3) {
    asm volatile("ldmatrix.sync.aligned.m8n8.x4.shared.b16 {%0,%1,%2,%3}, [%4];\n"
                 : "=r"(r0), "=r"(r1), "=r"(r2), "=r"(r3) : "r"(addr));
}
__device__ __forceinline__ void mma_bf16(float* c, const uint32_t* a, uint32_t b0, uint32_t b1) {
    asm volatile(
        "mma.sync.aligned.m16n8k16.row.col.f32.bf16.bf16.f32 "
        "{%0,%1,%2,%3}, {%4,%5,%6,%7}, {%8,%9}, {%0,%1,%2,%3};\n"
        : "+f"(c[0]), "+f"(c[1]), "+f"(c[2]), "+f"(c[3])
        : "r"(a[0]), "r"(a[1]), "r"(a[2]), "r"(a[3]), "r"(b0), "r"(b1));
}

// fetch one 128x32 fp32 tile into registers (4 x float4 per thread)
__device__ __forceinline__ void fetch_tile(
    const float* __restrict__ G, int row0, int row_limit, int ldk, int k0,
    int tid, float4 (&v)[4])
{
    int fr = tid >> 3, fc = tid & 7;
#pragma unroll
    for (int s = 0; s < 4; ++s) {
        int grow = row0 + s * 32 + fr;
        v[s] = make_float4(0.f, 0.f, 0.f, 0.f);
        if (grow < row_limit)
            v[s] = *(const float4*)&G[(size_t)grow * ldk + k0 + fc * 4];
    }
}
// fetch packed W2 tile: rows 0..63 <- W2l, 64..127 <- W2r (ldk = DH)
__device__ __forceinline__ void fetch_tile_w2(
    const float* __restrict__ W2l, const float* __restrict__ W2r, int k0,
    int tid, float4 (&v)[4])
{
    int fr = tid >> 3, fc = tid & 7;
#pragma unroll
    for (int s = 0; s < 4; ++s) {
        int row = s * 32 + fr;
        const float* src = (row < DOUT) ? &W2l[(size_t)row * DH]
                                        : &W2r[(size_t)(row - DOUT) * DH];
        v[s] = *(const float4*)&src[k0 + fc * 4];
    }
}
// split regs -> hi/lo bf16 smem tile
__device__ __forceinline__ void store_split(
    const float4 (&v)[4], __nv_bfloat16* hi, __nv_bfloat16* lo, int tid)
{
    int fr = tid >> 3, fc = tid & 7;
#pragma unroll
    for (int s = 0; s < 4; ++s) {
        int row = s * 32 + fr;
        __nv_bfloat16 h0, l0, h1, l1, h2, l2, h3, l3;
        split2(v[s].x, h0, l0); split2(v[s].y, h1, l1);
        split2(v[s].z, h2, l2); split2(v[s].w, h3, l3);
        *(uint32_t*)&hi[row * SM_LD + fc * 4]     = pack_bf16x2(h0, h1);
        *(uint32_t*)&hi[row * SM_LD + fc * 4 + 2] = pack_bf16x2(h2, h3);
        *(uint32_t*)&lo[row * SM_LD + fc * 4]     = pack_bf16x2(l0, l1);
        *(uint32_t*)&lo[row * SM_LD + fc * 4 + 2] = pack_bf16x2(l2, l3);
    }
}

// one k16 step: C += Ahi*Bhi + Ahi*Blo + Alo*Bhi
__device__ __forceinline__ void mma_k16(
    float (&c)[2][8][4],
    const __nv_bfloat16* Ahi, const __nv_bfloat16* Alo,
    const __nv_bfloat16* Bhi, const __nv_bfloat16* Blo,
    int m_local, int n_local, int lane, int k16)
{
    const int aRow = (lane & 7) + ((lane >> 3) & 1) * 8;
    const int aCol = k16 + (lane >> 4) * 8;
    const int bRow = (lane & 7) + ((lane >> 4) & 1) * 8;
    const int bCol = k16 + ((lane >> 3) & 1) * 8;
    uint32_t baseAhi = (uint32_t)__cvta_generic_to_shared(Ahi);
    uint32_t baseAlo = (uint32_t)__cvta_generic_to_shared(Alo);
    uint32_t baseBhi = (uint32_t)__cvta_generic_to_shared(Bhi);
    uint32_t baseBlo = (uint32_t)__cvta_generic_to_shared(Blo);

    uint32_t ah[2][4], al[2][4], bh[4][4], bl[4][4];
#pragma unroll
    for (int i = 0; i < 2; ++i)
        lds_x4(baseAhi + ((m_local + 16 * i + aRow) * SM_LD + aCol) * 2,
               ah[i][0], ah[i][1], ah[i][2], ah[i][3]);
#pragma unroll
    for (int jj = 0; jj < 4; ++jj)
        lds_x4(baseBhi + ((n_local + 16 * jj + bRow) * SM_LD + bCol) * 2,
               bh[jj][0], bh[jj][1], bh[jj][2], bh[jj][3]);
#pragma unroll
    for (int i = 0; i < 2; ++i)
#pragma unroll
        for (int j = 0; j < 8; ++j)
            mma_bf16(c[i][j], ah[i], bh[j >> 1][(j & 1) * 2], bh[j >> 1][(j & 1) * 2 + 1]);
#pragma unroll
    for (int jj = 0; jj < 4; ++jj)
        lds_x4(baseBlo + ((n_local + 16 * jj + bRow) * SM_LD + bCol) * 2,
               bl[jj][0], bl[jj][1], bl[jj][2], bl[jj][3]);
#pragma unroll
    for (int i = 0; i < 2; ++i)
#pragma unroll
        for (int j = 0; j < 8; ++j)
            mma_bf16(c[i][j], ah[i], bl[j >> 1][(j & 1) * 2], bl[j >> 1][(j & 1) * 2 + 1]);
#pragma unroll
    for (int i = 0; i < 2; ++i)
        lds_x4(baseAlo + ((m_local + 16 * i + aRow) * SM_LD + aCol) * 2,
               al[i][0], al[i][1], al[i][2], al[i][3]);
#pragma unroll
    for (int i = 0; i < 2; ++i)
#pragma unroll
        for (int j = 0; j < 8; ++j)
            mma_bf16(c[i][j], al[i], bh[j >> 1][(j & 1) * 2], bh[j >> 1][(j & 1) * 2 + 1]);
}

// Layer 1: h = relu( agg1 @ W1l^T + x @ W1r^T + b1 )   [M=50000, N=256, K=2x128]
__global__ void __launch_bounds__(256)
gemm1_mma_kernel(const float* __restrict__ x,
                 const float* __restrict__ W1l, const float* __restrict__ W1r,
                 const float* __restrict__ b1) {
    extern __shared__ __nv_bfloat16 sm[];
    const int tid = threadIdx.x;
    const int lane = tid & 31;
    const int wid = tid >> 5;
    const int m_local = (wid & 3) * 32;
    const int n_local = (wid >> 2) * 64;
    const int m0 = blockIdx.x * 128;
    const int n0 = blockIdx.y * 128;

    float c[2][8][4];
#pragma unroll
    for (int i = 0; i < 2; ++i)
#pragma unroll
        for (int j = 0; j < 8; ++j)
#pragma unroll
            for (int k = 0; k < 4; ++k) c[i][j][k] = 0.f;

    const float* Asrc[2] = {g_agg1, x};
    const float* Wsrc[2] = {W1l, W1r};
    const int NCH = 8;  // 2 passes x 4 chunks

    float4 av[4], bv[4];
    // prologue: chunk 0 -> buf 0
    fetch_tile(Asrc[0], m0, N_NODES, DIN, 0, tid, av);
    fetch_tile(Wsrc[0], n0, 1 << 30, DIN, 0, tid, bv);
    {
        __nv_bfloat16* b = sm;
        store_split(av, b, b + TILE_HALF, tid);
        store_split(bv, b + 2 * TILE_HALF, b + 3 * TILE_HALF, tid);
    }
    __syncthreads();

    for (int ch = 0; ch < NCH; ++ch) {
        int cur = ch & 1, nxt = cur ^ 1;
        if (ch + 1 < NCH) {
            int p = (ch + 1) >> 2, kc = ((ch + 1) & 3) * 32;
            fetch_tile(Asrc[p], m0, N_NODES, DIN, kc, tid, av);
            fetch_tile(Wsrc[p], n0, 1 << 30, DIN, kc, tid, bv);
        }
        __nv_bfloat16* bc = sm + cur * BUF_ELEMS;
        mma_k16(c, bc, bc + TILE_HALF, bc + 2 * TILE_HALF, bc + 3 * TILE_HALF,
                m_local, n_local, lane, 0);
        mma_k16(c, bc, bc + TILE_HALF, bc + 2 * TILE_HALF, bc + 3 * TILE_HALF,
                m_local, n_local, lane, 16);
        if (ch + 1 < NCH) {
            __nv_bfloat16* bn = sm + nxt * BUF_ELEMS;
            store_split(av, bn, bn + TILE_HALF, tid);
            store_split(bv, bn + 2 * TILE_HALF, bn + 3 * TILE_HALF, tid);
            __syncthreads();
        }
    }
    // epilogue: +bias, relu -> g_h
    const int gid = lane >> 2, tig = lane & 3;
#pragma unroll
    for (int i = 0; i < 2; ++i) {
        int row = m0 + m_local + 16 * i + gid;
#pragma unroll
        for (int j = 0; j < 8; ++j) {
            int col = n0 + n_local + 8 * j + 2 * tig;
            float bb0 = b1[col], bb1 = b1[col + 1];
            if (row < N_NODES) {
                float2 o = make_float2(fmaxf(c[i][j][0] + bb0, 0.f),
                                       fmaxf(c[i][j][1] + bb1, 0.f));
                *(float2*)&g_h[(size_t)row * DH + col] = o;
            }
            if (row + 8 < N_NODES) {
                float2 o = make_float2(fmaxf(c[i][j][2] + bb0, 0.f),
                                       fmaxf(c[i][j][3] + bb1, 0.f));
                *(float2*)&g_h[(size_t)(row + 8) * DH + col] = o;
            }
        }
    }
}

// Layer 2 projections: P[:,0:64] = h @ W2l^T ; P[:,64:128] = h @ W2r^T  [K=256]
__global__ void __launch_bounds__(256)
gemm2_mma_kernel(const float* __restrict__ W2l, const float* __restrict__ W2r) {
    extern __shared__ __nv_bfloat16 sm[];
    const int tid = threadIdx.x;
    const int lane = tid & 31;
    const int wid = tid >> 5;
    const int m_local = (wid & 3) * 32;
    const int n_local = (wid >> 2) * 64;
    const int m0 = blockIdx.x * 128;

    float c[2][8][4];
#pragma unroll
    for (int i = 0; i < 2; ++i)
#pragma unroll
        for (int j = 0; j < 8; ++j)
#pragma unroll
            for (int k = 0; k < 4; ++k) c[i][j][k] = 0.f;

    const int NCH = DH / 32;  // 8

    float4 av[4], bv[4];
    fetch_tile(g_h, m0, N_NODES, DH, 0, tid, av);
    fetch_tile_w2(W2l, W2r, 0, tid, bv);
    {
        __nv_bfloat16* b = sm;
        store_split(av, b, b + TILE_HALF, tid);
        store_split(bv, b + 2 * TILE_HALF, b + 3 * TILE_HALF, tid);
    }
    __syncthreads();

    for (int ch = 0; ch < NCH; ++ch) {
        int cur = ch & 1, nxt = cur ^ 1;
        if (ch + 1 < NCH) {
            int kc = (ch + 1) * 32;
            fetch_tile(g_h, m0, N_NODES, DH, kc, tid, av);
            fetch_tile_w2(W2l, W2r, kc, tid, bv);
        }
        __nv_bfloat16* bc = sm + cur * BUF_ELEMS;
        mma_k16(c, bc, bc + TILE_HALF, bc + 2 * TILE_HALF, bc + 3 * TILE_HALF,
                m_local, n_local, lane, 0);
        mma_k16(c, bc, bc + TILE_HALF, bc + 2 * TILE_HALF, bc + 3 * TILE_HALF,
                m_local, n_local, lane, 16);
        if (ch + 1 < NCH) {
            __nv_bfloat16* bn = sm + nxt * BUF_ELEMS;
            store_split(av, bn, bn + TILE_HALF, tid);
            store_split(bv, bn + 2 * TILE_HALF, bn + 3 * TILE_HALF, tid);
            __syncthreads();
        }
    }
    const int gid = lane >> 2, tig = lane & 3;
#pragma unroll
    for (int i = 0; i < 2; ++i) {
        int row = m0 + m_local + 16 * i + gid;
#pragma unroll
        for (int j = 0; j < 8; ++j) {
            int col = n_local + 8 * j + 2 * tig;
            if (row < N_NODES)
                *(float2*)&g_P[(size_t)row * 2 * DOUT + col] =
                    make_float2(c[i][j][0], c[i][j][1]);
            if (row + 8 < N_NODES)
                *(float2*)&g_P[(size_t)(row + 8) * 2 * DOUT + col] =
                    make_float2(c[i][j][2], c[i][j][3]);
        }
    }
}

// ---- layer-2 aggregation + combine (gather, warp per node) --------------------
__global__ void __launch_bounds__(256)
agg2_final_kernel(const float* __restrict__ b2, float* __restrict__ out) {
    int w    = (blockIdx.x * blockDim.x + threadIdx.x) >> 5;
    int lane = threadIdx.x & 31;
    if (w >= N_NODES) return;
    int start = g_rowptr[w], end = g_rowptr[w + 1];
    const float2* Pv = (const float2*)g_P;
    float2 acc = make_float2(0.f, 0.f);
    int p = start;
    for (; p + 4 <= end; p += 4) {
        int s0 = g_col[p], s1 = g_col[p + 1], s2 = g_col[p + 2], s3 = g_col[p + 3];
        float2 v0 = Pv[(long long)s0 * 64 + lane];
        float2 v1 = Pv[(long long)s1 * 64 + lane];
        float2 v2 = Pv[(long long)s2 * 64 + lane];
        float2 v3 = Pv[(long long)s3 * 64 + lane];
        acc.x += v0.x + v1.x + v2.x + v3.x;
        acc.y += v0.y + v1.y + v2.y + v3.y;
    }
    for (; p < end; ++p) {
        float2 v = Pv[(long long)g_col[p] * 64 + lane];
        acc.x += v.x; acc.y += v.y;
    }
    float inv = g_inv[w];
    float2 root = Pv[(long long)w * 64 + 32 + lane];
    float2 bias = ((const float2*)b2)[lane];
    float2 o;
    o.x = acc.x * inv + root.x + bias.x;
    o.y = acc.y * inv + root.y + bias.y;
    ((float2*)out)[(long long)w * 32 + lane] = o;
}

// ---------------- launch --------------------------------------------------------
extern "C" void kernel_launch(void* const* d_in, const int* in_sizes, int n_in,
                              void* d_out, int out_size) {
    const float* x   = (const float*)d_in[0];
    const void*  ei  = d_in[1];
    const float* W1l = (const float*)d_in[2];
    const float* W1r = (const float*)d_in[3];
    const float* b1  = (const float*)d_in[4];
    const float* W2l = (const float*)d_in[5];
    const float* W2r = (const float*)d_in[6];
    const float* b2  = (const float*)d_in[7];
    float*       out = (float*)d_out;

    const int SMEM = 2 * BUF_ELEMS * 2;  // 81920 B
    cudaFuncSetAttribute(gemm1_mma_kernel,
                         cudaFuncAttributeMaxDynamicSharedMemorySize, SMEM);
    cudaFuncSetAttribute(gemm2_mma_kernel,
                         cudaFuncAttributeMaxDynamicSharedMemorySize, SMEM);

    zero_cnt_detect_kernel<<<(N_NODES + 255) / 256, 256>>>((const unsigned int*)ei);
    count_kernel<<<(N_EDGES + 255) / 256, 256>>>(ei);
    blocksum_kernel<<<NB_SCAN, 256>>>();
    bscan_kernel<<<1, 64>>>();
    rowptr_kernel<<<NB_SCAN, 256>>>();
    fill_kernel<<<(N_EDGES + 255) / 256, 256>>>(ei);

    agg1_kernel<<<(N_NODES * 32 + 255) / 256, 256>>>(x);
    {
        dim3 grid((N_NODES + 127) / 128, 2);
        gemm1_mma_kernel<<<grid, 256, SMEM>>>(x, W1l, W1r, b1);
    }
    {
        dim3 grid((N_NODES + 127) / 128, 1);
        gemm2_mma_kernel<<<grid, 256, SMEM>>>(W2l, W2r);
    }
    agg2_final_kernel<<<(N_NODES * 32 + 255) / 256, 256>>>(b2, out);
}

// round 7
// speedup vs baseline: 1.0866x; 1.0866x over previous
#include <cuda_runtime.h>
#include <cuda_bf16.h>
#include <cstdint>

#define N_NODES 50000
#define N_PAD   50176   // 392 * 128, padded rows (zero-initialized, never written)
#define N_EDGES 800000
#define DIN 128
#define DH  256
#define DOUT 64
#define NB_SCAN 49      // ceil(50000/1024)

// ---------------- scratch ------------------------------------------------------
__device__ __align__(16) float g_inv [N_NODES];
__device__ __align__(16) float g_P   [N_NODES * 2*DOUT];
// pre-split bf16 operands (hi/lo)
__device__ __align__(16) __nv_bfloat16 g_a1h[N_PAD * DIN];
__device__ __align__(16) __nv_bfloat16 g_a1l[N_PAD * DIN];
__device__ __align__(16) __nv_bfloat16 g_xh [N_PAD * DIN];
__device__ __align__(16) __nv_bfloat16 g_xl [N_PAD * DIN];
__device__ __align__(16) __nv_bfloat16 g_hh [N_PAD * DH];
__device__ __align__(16) __nv_bfloat16 g_hl [N_PAD * DH];
__device__ __align__(16) __nv_bfloat16 g_w1h[512 * DIN];   // rows 0..255 W1l, 256..511 W1r
__device__ __align__(16) __nv_bfloat16 g_w1l[512 * DIN];
__device__ __align__(16) __nv_bfloat16 g_w2h[128 * DH];    // rows 0..63 W2l, 64..127 W2r
__device__ __align__(16) __nv_bfloat16 g_w2l[128 * DH];
__device__ int g_rowptr[N_NODES + 1];
__device__ int g_cnt   [N_NODES];
__device__ int g_col   [N_EDGES];
__device__ int g_bsum  [64];
__device__ int g_boff  [64];
__device__ int g_is64;

static __device__ __forceinline__ uint32_t pack_bf16x2(__nv_bfloat16 a, __nv_bfloat16 b) {
    return (uint32_t)__bfloat16_as_ushort(a) | ((uint32_t)__bfloat16_as_ushort(b) << 16);
}
static __device__ __forceinline__ void split2(float v, __nv_bfloat16& h, __nv_bfloat16& l) {
    h = __float2bfloat16(v);
    l = __float2bfloat16(v - __bfloat162float(h));
}

// ---------------- zero counts + edge dtype detect (fused) ----------------------
__global__ void zero_cnt_detect_kernel(const unsigned int* __restrict__ ei_words) {
    int i = blockIdx.x * blockDim.x + threadIdx.x;
    if (i < N_NODES) g_cnt[i] = 0;
    if (i == 0) {
        int is64 = 1;
        for (int k = 0; k < 128; ++k)
            if (ei_words[2 * k + 1] != 0u) { is64 = 0; break; }
        g_is64 = is64;
    }
}
__device__ __forceinline__ long long edge_val(const void* ei, long long idx) {
    if (g_is64) return ((const long long*)ei)[idx];
    return (long long)((const int*)ei)[idx];
}

__global__ void count_kernel(const void* __restrict__ ei) {
    int e = blockIdx.x * blockDim.x + threadIdx.x;
    if (e >= N_EDGES) return;
    long long d = edge_val(ei, N_EDGES + e);
    if ((unsigned long long)d < N_NODES) atomicAdd(&g_cnt[(int)d], 1);
}

__global__ void blocksum_kernel() {
    int b = blockIdx.x, t = threadIdx.x;
    int i0 = b * 1024 + t * 4;
    int s = 0;
#pragma unroll
    for (int k = 0; k < 4; ++k) { int i = i0 + k; if (i < N_NODES) s += g_cnt[i]; }
    for (int off = 16; off > 0; off >>= 1) s += __shfl_down_sync(0xffffffffu, s, off);
    __shared__ int ws[8];
    int lane = t & 31, w = t >> 5;
    if (lane == 0) ws[w] = s;
    __syncthreads();
    if (t == 0) { int tot = 0; for (int k = 0; k < 8; ++k) tot += ws[k]; g_bsum[b] = tot; }
}
__global__ void bscan_kernel() {
    __shared__ int sv[64];
    int t = threadIdx.x;
    int v = (t < NB_SCAN) ? g_bsum[t] : 0;
    sv[t] = v;
    __syncthreads();
    for (int off = 1; off < 64; off <<= 1) {
        int u = (t >= off) ? sv[t - off] : 0;
        __syncthreads();
        sv[t] += u;
        __syncthreads();
    }
    g_boff[t] = sv[t] - v;
}
__global__ void rowptr_kernel() {
    __shared__ int warp_tot[8];
    __shared__ int warp_off[8];
    int b = blockIdx.x, t = threadIdx.x;
    int lane = t & 31, w = t >> 5;
    int i0 = b * 1024 + t * 4;
    int c[4];
#pragma unroll
    for (int k = 0; k < 4; ++k) { int i = i0 + k; c[k] = (i < N_NODES) ? g_cnt[i] : 0; }
    int s = c[0] + c[1] + c[2] + c[3];
    int pre = s;
    for (int off = 1; off < 32; off <<= 1) {
        int n = __shfl_up_sync(0xffffffffu, pre, off);
        if (lane >= off) pre += n;
    }
    if (lane == 31) warp_tot[w] = pre;
    __syncthreads();
    if (w == 0) {
        int v = (lane < 8) ? warp_tot[lane] : 0;
        int orig = v;
        for (int off = 1; off < 8; off <<= 1) {
            int n = __shfl_up_sync(0xffffffffu, v, off);
            if (lane >= off) v += n;
        }
        if (lane < 8) warp_off[lane] = v - orig;
    }
    __syncthreads();
    int r = g_boff[b] + warp_off[w] + (pre - s);
#pragma unroll
    for (int k = 0; k < 4; ++k) {
        int i = i0 + k;
        if (i < N_NODES) {
            g_rowptr[i] = r;
            g_cnt[i]    = r;
            g_inv[i]    = 1.0f / (float)(c[k] > 0 ? c[k] : 1);
            r += c[k];
            if (i == N_NODES - 1) g_rowptr[N_NODES] = r;
        }
    }
}
__global__ void fill_kernel(const void* __restrict__ ei) {
    int e = blockIdx.x * blockDim.x + threadIdx.x;
    if (e >= N_EDGES) return;
    long long s = edge_val(ei, e);
    long long d = edge_val(ei, N_EDGES + e);
    if ((unsigned long long)s >= N_NODES || (unsigned long long)d >= N_NODES) return;
    int pos = atomicAdd(&g_cnt[(int)d], 1);
    g_col[pos] = (int)s;
}

// ---------------- operand pre-splits -------------------------------------------
// weights: W1l,W1r -> g_w1h/l (512x128); W2l,W2r -> g_w2h/l (128x256)
__global__ void split_w_kernel(const float* __restrict__ W1l, const float* __restrict__ W1r,
                               const float* __restrict__ W2l, const float* __restrict__ W2r) {
    int idx = blockIdx.x * blockDim.x + threadIdx.x;
    const int T1 = 512 * DIN;           // 65536
    const int T2 = 128 * DH;            // 32768
    if (idx < T1) {
        int row = idx >> 7, col = idx & 127;
        float v = (row < 256) ? W1l[row * DIN + col] : W1r[(row - 256) * DIN + col];
        __nv_bfloat16 h, l; split2(v, h, l);
        g_w1h[idx] = h; g_w1l[idx] = l;
    } else if (idx < T1 + T2) {
        int j = idx - T1;
        int row = j >> 8, col = j & 255;
        float v = (row < DOUT) ? W2l[row * DH + col] : W2r[(row - DOUT) * DH + col];
        __nv_bfloat16 h, l; split2(v, h, l);
        g_w2h[j] = h; g_w2l[j] = l;
    }
}
// x -> g_xh/g_xl
__global__ void split_x_kernel(const float* __restrict__ x) {
    int idx = blockIdx.x * blockDim.x + threadIdx.x;   // float4 units
    if (idx >= N_NODES * (DIN / 4)) return;
    float4 v = ((const float4*)x)[idx];
    __nv_bfloat16 h0, l0, h1, l1, h2, l2, h3, l3;
    split2(v.x, h0, l0); split2(v.y, h1, l1);
    split2(v.z, h2, l2); split2(v.w, h3, l3);
    *(uint2*)&g_xh[idx * 4] = make_uint2(pack_bf16x2(h0, h1), pack_bf16x2(h2, h3));
    *(uint2*)&g_xl[idx * 4] = make_uint2(pack_bf16x2(l0, l1), pack_bf16x2(l2, l3));
}

// ---------------- layer-1 aggregation (gather, warp per node, writes hi/lo) ----
__global__ void __launch_bounds__(256)
agg1_kernel(const float* __restrict__ x) {
    int w    = (blockIdx.x * blockDim.x + threadIdx.x) >> 5;
    int lane = threadIdx.x & 31;
    if (w >= N_NODES) return;
    int start = g_rowptr[w], end = g_rowptr[w + 1];
    const float4* xv = (const float4*)x;
    float4 acc = make_float4(0.f, 0.f, 0.f, 0.f);
    int p = start;
    for (; p + 4 <= end; p += 4) {
        int s0 = g_col[p], s1 = g_col[p + 1], s2 = g_col[p + 2], s3 = g_col[p + 3];
        float4 v0 = xv[(long long)s0 * 32 + lane];
        float4 v1 = xv[(long long)s1 * 32 + lane];
        float4 v2 = xv[(long long)s2 * 32 + lane];
        float4 v3 = xv[(long long)s3 * 32 + lane];
        acc.x += v0.x + v1.x + v2.x + v3.x;
        acc.y += v0.y + v1.y + v2.y + v3.y;
        acc.z += v0.z + v1.z + v2.z + v3.z;
        acc.w += v0.w + v1.w + v2.w + v3.w;
    }
    for (; p < end; ++p) {
        float4 v = xv[(long long)g_col[p] * 32 + lane];
        acc.x += v.x; acc.y += v.y; acc.z += v.z; acc.w += v.w;
    }
    float inv = g_inv[w];
    acc.x *= inv; acc.y *= inv; acc.z *= inv; acc.w *= inv;
    __nv_bfloat16 h0, l0, h1, l1, h2, l2, h3, l3;
    split2(acc.x, h0, l0); split2(acc.y, h1, l1);
    split2(acc.z, h2, l2); split2(acc.w, h3, l3);
    size_t off = (size_t)w * DIN + lane * 4;
    *(uint2*)&g_a1h[off] = make_uint2(pack_bf16x2(h0, h1), pack_bf16x2(h2, h3));
    *(uint2*)&g_a1l[off] = make_uint2(pack_bf16x2(l0, l1), pack_bf16x2(l2, l3));
}

// ================= bf16x3 HMMA GEMM, cp.async double-buffered ===================
// block tile 128x128, 8 warps, warp tile 32x64, K-chunk 32 (2 k16 steps)
#define SM_LD 40                         // bf16 row stride (32 + 8 pad)
#define TILE_B (128 * SM_LD * 2)         // 10240 B per tile
#define BUF_B  (4 * TILE_B)              // Ahi,Alo,Bhi,Blo = 40960 B
#define SMEM_TOTAL (2 * BUF_B)           // 81920 B

static __device__ __forceinline__ void cp16(uint32_t dst, const void* src) {
    asm volatile("cp.async.cg.shared.global [%0], [%1], 16;" :: "r"(dst), "l"(src));
}
static __device__ __forceinline__ void cp_commit() {
    asm volatile("cp.async.commit_group;");
}
template<int N> static __device__ __forceinline__ void cp_wait() {
    asm volatile("cp.async.wait_group %0;" :: "n"(N));
}
// copy one 128x32 bf16 tile (rowbytes apart in gmem) into padded smem tile
static __device__ __forceinline__ void cp_tile(
    uint32_t dst_tile, const __nv_bfloat16* src0, int rowbytes, int tid)
{
    const char* src = (const char*)src0;
#pragma unroll
    for (int r = 0; r < 2; ++r) {
        int c = tid + r * 256;        // 0..511
        int row = c >> 2, seg = c & 3;
        cp16(dst_tile + row * (SM_LD * 2) + seg * 16,
             src + (size_t)row * rowbytes + seg * 16);
    }
}

static __device__ __forceinline__ void lds_x4(uint32_t addr, uint32_t& r0, uint32_t& r1,
                                              uint32_t& r2, uint32_t& r3) {
    asm volatile("ldmatrix.sync.aligned.m8n8.x4.shared.b16 {%0,%1,%2,%3}, [%4];\n"
                 : "=r"(r0), "=r"(r1), "=r"(r2), "=r"(r3) : "r"(addr));
}
static __device__ __forceinline__ void mma_bf16(float* c, const uint32_t* a, uint32_t b0, uint32_t b1) {
    asm volatile(
        "mma.sync.aligned.m16n8k16.row.col.f32.bf16.bf16.f32 "
        "{%0,%1,%2,%3}, {%4,%5,%6,%7}, {%8,%9}, {%0,%1,%2,%3};\n"
        : "+f"(c[0]), "+f"(c[1]), "+f"(c[2]), "+f"(c[3])
        : "r"(a[0]), "r"(a[1]), "r"(a[2]), "r"(a[3]), "r"(b0), "r"(b1));
}

// one k16 step: C += Ahi*Bhi + Ahi*Blo + Alo*Bhi   (tile bases are smem u32)
static __device__ __forceinline__ void mma_k16(
    float (&c)[2][8][4], uint32_t Ahi, uint32_t Alo, uint32_t Bhi, uint32_t Blo,
    int m_local, int n_local, int lane, int k16)
{
    const int aRow = (lane & 7) + ((lane >> 3) & 1) * 8;
    const int aCol = k16 + (lane >> 4) * 8;
    const int bRow = (lane & 7) + ((lane >> 4) & 1) * 8;
    const int bCol = k16 + ((lane >> 3) & 1) * 8;

    uint32_t ah[2][4], al[2][4], bh[4][4], bl[4][4];
#pragma unroll
    for (int i = 0; i < 2; ++i)
        lds_x4(Ahi + ((m_local + 16 * i + aRow) * SM_LD + aCol) * 2,
               ah[i][0], ah[i][1], ah[i][2], ah[i][3]);
#pragma unroll
    for (int jj = 0; jj < 4; ++jj)
        lds_x4(Bhi + ((n_local + 16 * jj + bRow) * SM_LD + bCol) * 2,
               bh[jj][0], bh[jj][1], bh[jj][2], bh[jj][3]);
#pragma unroll
    for (int i = 0; i < 2; ++i)
#pragma unroll
        for (int j = 0; j < 8; ++j)
            mma_bf16(c[i][j], ah[i], bh[j >> 1][(j & 1) * 2], bh[j >> 1][(j & 1) * 2 + 1]);
#pragma unroll
    for (int jj = 0; jj < 4; ++jj)
        lds_x4(Blo + ((n_local + 16 * jj + bRow) * SM_LD + bCol) * 2,
               bl[jj][0], bl[jj][1], bl[jj][2], bl[jj][3]);
#pragma unroll
    for (int i = 0; i < 2; ++i)
#pragma unroll
        for (int j = 0; j < 8; ++j)
            mma_bf16(c[i][j], ah[i], bl[j >> 1][(j & 1) * 2], bl[j >> 1][(j & 1) * 2 + 1]);
#pragma unroll
    for (int i = 0; i < 2; ++i)
        lds_x4(Alo + ((m_local + 16 * i + aRow) * SM_LD + aCol) * 2,
               al[i][0], al[i][1], al[i][2], al[i][3]);
#pragma unroll
    for (int i = 0; i < 2; ++i)
#pragma unroll
        for (int j = 0; j < 8; ++j)
            mma_bf16(c[i][j], al[i], bh[j >> 1][(j & 1) * 2], bh[j >> 1][(j & 1) * 2 + 1]);
}

// issue all four tiles of chunk ch for gemm1 into buffer
static __device__ __forceinline__ void g1_issue(
    uint32_t smb, int buf, int ch, int m0, int n0, int tid)
{
    int p = ch >> 2;                 // 0: agg1/W1l, 1: x/W1r
    int kcol = (ch & 3) * 32;
    uint32_t b = smb + buf * BUF_B;
    const __nv_bfloat16* Ah = (p ? g_xh : g_a1h) + (size_t)m0 * DIN + kcol;
    const __nv_bfloat16* Al = (p ? g_xl : g_a1l) + (size_t)m0 * DIN + kcol;
    const __nv_bfloat16* Bh = g_w1h + (size_t)(p * 256 + n0) * DIN + kcol;
    const __nv_bfloat16* Bl = g_w1l + (size_t)(p * 256 + n0) * DIN + kcol;
    cp_tile(b,              Ah, DIN * 2, tid);
    cp_tile(b + TILE_B,     Al, DIN * 2, tid);
    cp_tile(b + 2 * TILE_B, Bh, DIN * 2, tid);
    cp_tile(b + 3 * TILE_B, Bl, DIN * 2, tid);
    cp_commit();
}
static __device__ __forceinline__ void g2_issue(
    uint32_t smb, int buf, int ch, int m0, int tid)
{
    int kcol = ch * 32;
    uint32_t b = smb + buf * BUF_B;
    cp_tile(b,              g_hh + (size_t)m0 * DH + kcol, DH * 2, tid);
    cp_tile(b + TILE_B,     g_hl + (size_t)m0 * DH + kcol, DH * 2, tid);
    cp_tile(b + 2 * TILE_B, g_w2h + kcol, DH * 2, tid);
    cp_tile(b + 3 * TILE_B, g_w2l + kcol, DH * 2, tid);
    cp_commit();
}

// Layer 1: h = relu( agg1 @ W1l^T + x @ W1r^T + b1 ) -> g_hh/g_hl   grid(392, 2)
__global__ void __launch_bounds__(256)
gemm1_mma_kernel(const float* __restrict__ b1) {
    extern __shared__ char sm[];
    uint32_t smb = (uint32_t)__cvta_generic_to_shared(sm);
    const int tid = threadIdx.x, lane = tid & 31, wid = tid >> 5;
    const int m_local = (wid & 3) * 32;
    const int n_local = (wid >> 2) * 64;
    const int m0 = blockIdx.x * 128;
    const int n0 = blockIdx.y * 128;
    const int NCH = 8;

    float c[2][8][4];
#pragma unroll
    for (int i = 0; i < 2; ++i)
#pragma unroll
        for (int j = 0; j < 8; ++j)
#pragma unroll
            for (int k = 0; k < 4; ++k) c[i][j][k] = 0.f;

    g1_issue(smb, 0, 0, m0, n0, tid);
    for (int ch = 0; ch < NCH; ++ch) {
        int cur = ch & 1;
        if (ch + 1 < NCH) {
            g1_issue(smb, cur ^ 1, ch + 1, m0, n0, tid);
            cp_wait<1>();
        } else {
            cp_wait<0>();
        }
        __syncthreads();
        uint32_t b = smb + cur * BUF_B;
        mma_k16(c, b, b + TILE_B, b + 2 * TILE_B, b + 3 * TILE_B,
                m_local, n_local, lane, 0);
        mma_k16(c, b, b + TILE_B, b + 2 * TILE_B, b + 3 * TILE_B,
                m_local, n_local, lane, 16);
        __syncthreads();
    }
    // epilogue: +bias, relu, split -> g_hh/g_hl
    const int gid = lane >> 2, tig = lane & 3;
#pragma unroll
    for (int i = 0; i < 2; ++i) {
        int row = m0 + m_local + 16 * i + gid;
#pragma unroll
        for (int j = 0; j < 8; ++j) {
            int col = n0 + n_local + 8 * j + 2 * tig;
            float bb0 = b1[col], bb1 = b1[col + 1];
            if (row < N_NODES) {
                float v0 = fmaxf(c[i][j][0] + bb0, 0.f);
                float v1 = fmaxf(c[i][j][1] + bb1, 0.f);
                __nv_bfloat16 h0, l0, h1, l1;
                split2(v0, h0, l0); split2(v1, h1, l1);
                *(uint32_t*)&g_hh[(size_t)row * DH + col] = pack_bf16x2(h0, h1);
                *(uint32_t*)&g_hl[(size_t)row * DH + col] = pack_bf16x2(l0, l1);
            }
            if (row + 8 < N_NODES) {
                float v0 = fmaxf(c[i][j][2] + bb0, 0.f);
                float v1 = fmaxf(c[i][j][3] + bb1, 0.f);
                __nv_bfloat16 h0, l0, h1, l1;
                split2(v0, h0, l0); split2(v1, h1, l1);
                *(uint32_t*)&g_hh[(size_t)(row + 8) * DH + col] = pack_bf16x2(h0, h1);
                *(uint32_t*)&g_hl[(size_t)(row + 8) * DH + col] = pack_bf16x2(l0, l1);
            }
        }
    }
}

// Layer 2 projections: P = h @ [W2l;W2r]^T -> g_P (fp32)   grid(392, 1)
__global__ void __launch_bounds__(256)
gemm2_mma_kernel() {
    extern __shared__ char sm[];
    uint32_t smb = (uint32_t)__cvta_generic_to_shared(sm);
    const int tid = threadIdx.x, lane = tid & 31, wid = tid >> 5;
    const int m_local = (wid & 3) * 32;
    const int n_local = (wid >> 2) * 64;
    const int m0 = blockIdx.x * 128;
    const int NCH = 8;

    float c[2][8][4];
#pragma unroll
    for (int i = 0; i < 2; ++i)
#pragma unroll
        for (int j = 0; j < 8; ++j)
#pragma unroll
            for (int k = 0; k < 4; ++k) c[i][j][k] = 0.f;

    g2_issue(smb, 0, 0, m0, tid);
    for (int ch = 0; ch < NCH; ++ch) {
        int cur = ch & 1;
        if (ch + 1 < NCH) {
            g2_issue(smb, cur ^ 1, ch + 1, m0, tid);
            cp_wait<1>();
        } else {
            cp_wait<0>();
        }
        __syncthreads();
        uint32_t b = smb + cur * BUF_B;
        mma_k16(c, b, b + TILE_B, b + 2 * TILE_B, b + 3 * TILE_B,
                m_local, n_local, lane, 0);
        mma_k16(c, b, b + TILE_B, b + 2 * TILE_B, b + 3 * TILE_B,
                m_local, n_local, lane, 16);
        __syncthreads();
    }
    const int gid = lane >> 2, tig = lane & 3;
#pragma unroll
    for (int i = 0; i < 2; ++i) {
        int row = m0 + m_local + 16 * i + gid;
#pragma unroll
        for (int j = 0; j < 8; ++j) {
            int col = n_local + 8 * j + 2 * tig;
            if (row < N_NODES)
                *(float2*)&g_P[(size_t)row * 2 * DOUT + col] =
                    make_float2(c[i][j][0], c[i][j][1]);
            if (row + 8 < N_NODES)
                *(float2*)&g_P[(size_t)(row + 8) * 2 * DOUT + col] =
                    make_float2(c[i][j][2], c[i][j][3]);
        }
    }
}

// ---- layer-2 aggregation + combine (gather, warp per node) --------------------
__global__ void __launch_bounds__(256)
agg2_final_kernel(const float* __restrict__ b2, float* __restrict__ out) {
    int w    = (blockIdx.x * blockDim.x + threadIdx.x) >> 5;
    int lane = threadIdx.x & 31;
    if (w >= N_NODES) return;
    int start = g_rowptr[w], end = g_rowptr[w + 1];
    const float2* Pv = (const float2*)g_P;
    float2 acc = make_float2(0.f, 0.f);
    int p = start;
    for (; p + 4 <= end; p += 4) {
        int s0 = g_col[p], s1 = g_col[p + 1], s2 = g_col[p + 2], s3 = g_col[p + 3];
        float2 v0 = Pv[(long long)s0 * 64 + lane];
        float2 v1 = Pv[(long long)s1 * 64 + lane];
        float2 v2 = Pv[(long long)s2 * 64 + lane];
        float2 v3 = Pv[(long long)s3 * 64 + lane];
        acc.x += v0.x + v1.x + v2.x + v3.x;
        acc.y += v0.y + v1.y + v2.y + v3.y;
    }
    for (; p < end; ++p) {
        float2 v = Pv[(long long)g_col[p] * 64 + lane];
        acc.x += v.x; acc.y += v.y;
    }
    float inv = g_inv[w];
    float2 root = Pv[(long long)w * 64 + 32 + lane];
    float2 bias = ((const float2*)b2)[lane];
    float2 o;
    o.x = acc.x * inv + root.x + bias.x;
    o.y = acc.y * inv + root.y + bias.y;
    ((float2*)out)[(long long)w * 32 + lane] = o;
}

// ---------------- launch --------------------------------------------------------
extern "C" void kernel_launch(void* const* d_in, const int* in_sizes, int n_in,
                              void* d_out, int out_size) {
    const float* x   = (const float*)d_in[0];
    const void*  ei  = d_in[1];
    const float* W1l = (const float*)d_in[2];
    const float* W1r = (const float*)d_in[3];
    const float* b1  = (const float*)d_in[4];
    const float* W2l = (const float*)d_in[5];
    const float* W2r = (const float*)d_in[6];
    const float* b2  = (const float*)d_in[7];
    float*       out = (float*)d_out;

    cudaFuncSetAttribute(gemm1_mma_kernel,
                         cudaFuncAttributeMaxDynamicSharedMemorySize, SMEM_TOTAL);
    cudaFuncSetAttribute(gemm2_mma_kernel,
                         cudaFuncAttributeMaxDynamicSharedMemorySize, SMEM_TOTAL);

    zero_cnt_detect_kernel<<<(N_NODES + 255) / 256, 256>>>((const unsigned int*)ei);
    split_w_kernel<<<(512 * DIN + 128 * DH + 255) / 256, 256>>>(W1l, W1r, W2l, W2r);
    split_x_kernel<<<(N_NODES * (DIN / 4) + 255) / 256, 256>>>(x);
    count_kernel<<<(N_EDGES + 255) / 256, 256>>>(ei);
    blocksum_kernel<<<NB_SCAN, 256>>>();
    bscan_kernel<<<1, 64>>>();
    rowptr_kernel<<<NB_SCAN, 256>>>();
    fill_kernel<<<(N_EDGES + 255) / 256, 256>>>(ei);

    agg1_kernel<<<(N_NODES * 32 + 255) / 256, 256>>>(x);
    {
        dim3 grid(N_PAD / 128, 2);
        gemm1_mma_kernel<<<grid, 256, SMEM_TOTAL>>>(b1);
    }
    {
        dim3 grid(N_PAD / 128, 1);
        gemm2_mma_kernel<<<grid, 256, SMEM_TOTAL>>>();
    }
    agg2_final_kernel<<<(N_NODES * 32 + 255) / 256, 256>>>(b2, out);
}